// round 1
// baseline (speedup 1.0000x reference)
#include <cuda_runtime.h>
#include <cuda_bf16.h>

// 4096-point FWHT per row, 8192 rows, fp32.
// Decomposition: H4096 = H16(stride 256) * H16(stride 16) * H16(stride 1)
// (all butterfly stages commute; each acts on distinct index bits).
// One CTA of 256 threads per row; each thread does three 16-point
// register FWHTs with two shared-memory transposes in between.

#define NROW_ELEMS 4096
#define NTHREADS   256

// Skewed shared addressing: phys = idx + (idx>>4). 17-word "rows" make
// all three access patterns (stride 1 / 16 / 256 gathers) bank-conflict-free.
#define SKEW(idx) ((idx) + ((idx) >> 4))
#define SMEM_WORDS (4096 + 256)

__device__ __forceinline__ void fwht16(float* r) {
#pragma unroll
    for (int h = 1; h < 16; h <<= 1) {
#pragma unroll
        for (int j = 0; j < 16; j += 2 * h) {
#pragma unroll
            for (int k = 0; k < h; k++) {
                float a = r[j + k];
                float b = r[j + k + h];
                r[j + k]     = a + b;
                r[j + k + h] = a - b;
            }
        }
    }
}

__global__ void __launch_bounds__(NTHREADS)
fwht4096_kernel(const float* __restrict__ in, float* __restrict__ out) {
    __shared__ float s[SMEM_WORDS];

    const int t = threadIdx.x;
    const size_t row_off = (size_t)blockIdx.x * NROW_ELEMS;
    const float* __restrict__ x = in + row_off;
    float* __restrict__ y = out + row_off;

    float r[16];

    // ---- Round 1: strides 256..2048. Coalesced global load: lane t reads
    // x[k*256 + t] (consecutive lanes -> consecutive addresses).
#pragma unroll
    for (int k = 0; k < 16; k++)
        r[k] = x[k * 256 + t];
    fwht16(r);
#pragma unroll
    for (int k = 0; k < 16; k++) {
        int idx = k * 256 + t;
        s[SKEW(idx)] = r[k];
    }
    __syncthreads();

    // ---- Round 2: strides 16..128. Thread (a,c) owns idx = a*256 + b*16 + c.
    {
        const int a = t >> 4;
        const int c = t & 15;
#pragma unroll
        for (int b = 0; b < 16; b++) {
            int idx = a * 256 + b * 16 + c;
            r[b] = s[SKEW(idx)];
        }
        fwht16(r);
#pragma unroll
        for (int b = 0; b < 16; b++) {
            int idx = a * 256 + b * 16 + c;
            s[SKEW(idx)] = r[b];
        }
    }
    __syncthreads();

    // ---- Round 3: strides 1..8. Thread t owns 16 contiguous elements.
#pragma unroll
    for (int i = 0; i < 16; i++) {
        int idx = t * 16 + i;   // phys = t*17 + i : conflict-free
        r[i] = s[SKEW(idx)];
    }
    fwht16(r);

    // Scale by 1/sqrt(4096) = 1/64 (exact in fp32) and store coalesced 128-bit.
    const float scale = 1.0f / 64.0f;
    float4* y4 = reinterpret_cast<float4*>(y + t * 16);
#pragma unroll
    for (int v = 0; v < 4; v++) {
        float4 o;
        o.x = r[4 * v + 0] * scale;
        o.y = r[4 * v + 1] * scale;
        o.z = r[4 * v + 2] * scale;
        o.w = r[4 * v + 3] * scale;
        y4[v] = o;
    }
}

extern "C" void kernel_launch(void* const* d_in, const int* in_sizes, int n_in,
                              void* d_out, int out_size) {
    const float* x = (const float*)d_in[0];
    float* y = (float*)d_out;
    int total = in_sizes[0];
    int nrows = total / NROW_ELEMS;   // 8192
    fwht4096_kernel<<<nrows, NTHREADS>>>(x, y);
}